// round 9
// baseline (speedup 1.0000x reference)
#include <cuda_runtime.h>
#include <math.h>
#include <stdio.h>

#define N3 32768
#define HH 64
#define NK 48
#define NQ 4096
#define NPAIR (NQ*NK)

__device__ float2 g_tw[32];
__device__ float  g_lift[N3*256];
__device__ float  g_x[N3*HH];
__device__ float  g_tmp[N3*HH];
__device__ float2 g_A1[1024*8*64];
__device__ float2 g_A2[32*16*8*64];
__device__ float2 g_XF[16*16*8*64];
__device__ float2 g_YF[16*16*8*64];
__device__ float2 g_B1[32*16*8*64];
__device__ float2 g_B2[1024*8*64];
__device__ int g_cellcnt[4096], g_celloff[4097], g_fill[4096], g_bin[N3];
__device__ int g_cnt[NQ], g_qoff[NQ+1], g_pq[NPAIR], g_ps[NPAIR];
__device__ float g_H1[(size_t)NPAIR*512];
__device__ float g_H2[(size_t)NPAIR*256];
__device__ float g_K3[(size_t)NPAIR*64];
__device__ float g_gno[NQ*HH];
__device__ float g_P1[NQ*256];

__device__ __forceinline__ float gelu_f(float x) {
    float t = tanhf(0.7978845608028654f*(x + 0.044715f*x*x*x));
    return 0.5f*x*(1.0f + t);
}
__device__ __forceinline__ int cell_of(float x, float y, float z) {
    int ix = (int)(x*16.f); ix = ix<0?0:(ix>15?15:ix);
    int iy = (int)(y*16.f); iy = iy<0?0:(iy>15?15:iy);
    int iz = (int)(z*16.f); iz = iz<0?0:(iz>15?15:iz);
    return (ix*16+iy)*16+iz;
}

__global__ void k_init_tw() {
    int t = threadIdx.x;
    double a = -2.0*3.14159265358979323846*(double)t/32.0;
    g_tw[t] = make_float2((float)cos(a), (float)sin(a));
}
__global__ void k_zero_cells() {
    int i = blockIdx.x*blockDim.x + threadIdx.x;
    if (i < 4096) { g_cellcnt[i]=0; g_fill[i]=0; }
}
__global__ void k_count(const float* __restrict__ P) {
    int i = blockIdx.x*blockDim.x + threadIdx.x;
    if (i < N3) atomicAdd(&g_cellcnt[cell_of(P[i*3],P[i*3+1],P[i*3+2])], 1);
}
__device__ void scan4096(const int* __restrict__ in, int* __restrict__ out) {
    __shared__ int sh[1024];
    int t = threadIdx.x;
    int v0=in[t*4], v1=in[t*4+1], v2=in[t*4+2], v3=in[t*4+3];
    int p1=v0, p2=v0+v1, p3=p2+v2, s=p3+v3;
    sh[t]=s; __syncthreads();
    for (int off=1; off<1024; off<<=1) {
        int x = (t>=off) ? sh[t-off] : 0;
        __syncthreads(); sh[t]+=x; __syncthreads();
    }
    int base = sh[t]-s;
    out[t*4]=base; out[t*4+1]=base+p1; out[t*4+2]=base+p2; out[t*4+3]=base+p3;
    if (t==1023) out[4096]=sh[1023];
}
__global__ void k_scan_cells() { scan4096(g_cellcnt, g_celloff); }
__global__ void k_scan_pairs() { scan4096(g_cnt, g_qoff); }
__global__ void k_scatter(const float* __restrict__ P) {
    int i = blockIdx.x*blockDim.x + threadIdx.x;
    if (i >= N3) return;
    int c = cell_of(P[i*3],P[i*3+1],P[i*3+2]);
    g_bin[g_celloff[c] + atomicAdd(&g_fill[c],1)] = i;
}

template<int EMIT>
__device__ void knn_body(const float* __restrict__ P, const float* __restrict__ Q) {
    int q = blockIdx.x*blockDim.x + threadIdx.x;
    if (q >= NQ) return;
    float qx=Q[q*3], qy=Q[q*3+1], qz=Q[q*3+2];
    int cx=(int)(qx*16.f); cx=cx<0?0:(cx>15?15:cx);
    int cy=(int)(qy*16.f); cy=cy<0?0:(cy>15?15:cy);
    int cz=(int)(qz*16.f); cz=cz<0?0:(cz>15?15:cz);
    const float R2 = 0.0036f;
    float dl[NK]; int il[NK]; int m=0;
    for (int ox=(cx>0?cx-1:0); ox<=(cx<15?cx+1:15); ox++)
    for (int oy=(cy>0?cy-1:0); oy<=(cy<15?cy+1:15); oy++)
    for (int oz=(cz>0?cz-1:0); oz<=(cz<15?cz+1:15); oz++) {
        int c=(ox*16+oy)*16+oz;
        int s1=g_celloff[c+1];
        for (int p=g_celloff[c]; p<s1; p++) {
            int s=g_bin[p];
            float dx=qx-P[s*3], dy=qy-P[s*3+1], dz=qz-P[s*3+2];
            float d2=dx*dx+dy*dy+dz*dz;
            if (d2 < R2) {
                if (m < NK) {
                    int pos=m++;
                    while (pos>0 && dl[pos-1]>d2) { dl[pos]=dl[pos-1]; il[pos]=il[pos-1]; pos--; }
                    dl[pos]=d2; il[pos]=s;
                } else if (d2 < dl[NK-1]) {
                    int pos=NK-1;
                    while (pos>0 && dl[pos-1]>d2) { dl[pos]=dl[pos-1]; il[pos]=il[pos-1]; pos--; }
                    dl[pos]=d2; il[pos]=s;
                }
            }
        }
    }
    if (EMIT) {
        int off=g_qoff[q];
        for (int k=0;k<m;k++) { g_pq[off+k]=q; g_ps[off+k]=il[k]; }
    } else {
        g_cnt[q]=m;
    }
}
__global__ void k_knn(const float* __restrict__ P, const float* __restrict__ Q) { knn_body<0>(P,Q); }
__global__ void k_fill_pairs(const float* __restrict__ P, const float* __restrict__ Q) { knn_body<1>(P,Q); }

__global__ void k_lift1(const float* __restrict__ F, const float* __restrict__ P,
                        const float* __restrict__ W, const float* __restrict__ b) {
    int p = blockIdx.x, t = threadIdx.x;
    __shared__ float ft[6];
    if (t < 3) { ft[t]=F[p*3+t]; ft[3+t]=P[p*3+t]; }
    __syncthreads();
    float v = b[t];
    #pragma unroll
    for (int d=0; d<6; d++) v += ft[d]*W[d*256+t];
    g_lift[(size_t)p*256+t] = gelu_f(v);
}

template<int BM,int BN,int BK,int TM,int TN,bool DOGELU,bool PAIRLIM>
__global__ void k_gemm(const float* __restrict__ A, const float* __restrict__ B,
                       const float* __restrict__ b1, float* __restrict__ C,
                       int M, int N, int K) {
    int Meff = PAIRLIM ? g_qoff[NQ] : M;
    int mBase = blockIdx.y*BM;
    if (mBase >= Meff) return;
    int nBase = blockIdx.x*BN;
    constexpr int THREADS = (BM/TM)*(BN/TN);
    __shared__ float As[BK][BM+4];
    __shared__ float Bs[BK][BN];
    int tid = threadIdx.x;
    int tx = tid % (BN/TN), ty = tid / (BN/TN);
    float acc[TM][TN];
    #pragma unroll
    for (int i=0;i<TM;i++)
        #pragma unroll
        for (int j=0;j<TN;j++) acc[i][j]=0.f;
    for (int k0=0; k0<K; k0+=BK) {
        for (int i=tid; i<BM*BK; i+=THREADS) {
            int r=i/BK, c=i%BK, m=mBase+r;
            As[c][r] = (m<Meff) ? A[(size_t)m*K + k0 + c] : 0.f;
        }
        for (int i=tid; i<BK*BN; i+=THREADS) {
            int r=i/BN, c=i%BN;
            Bs[r][c] = B[(size_t)(k0+r)*N + nBase + c];
        }
        __syncthreads();
        #pragma unroll
        for (int kk=0; kk<BK; kk++) {
            float ra[TM], rb[TN];
            #pragma unroll
            for (int i=0;i<TM;i++) ra[i]=As[kk][ty*TM+i];
            #pragma unroll
            for (int j=0;j<TN;j++) rb[j]=Bs[kk][tx*TN+j];
            #pragma unroll
            for (int i=0;i<TM;i++)
                #pragma unroll
                for (int j=0;j<TN;j++) acc[i][j] += ra[i]*rb[j];
        }
        __syncthreads();
    }
    #pragma unroll
    for (int i=0;i<TM;i++) {
        int m = mBase + ty*TM + i;
        if (m >= Meff) continue;
        #pragma unroll
        for (int j=0;j<TN;j++) {
            int n = nBase + tx*TN + j;
            float v = acc[i][j] + b1[n];
            if (DOGELU) v = gelu_f(v);
            C[(size_t)m*N + n] = v;
        }
    }
}

__global__ void k_fft_z() {
    int xy = blockIdx.x;
    __shared__ float sx[32][64];
    int t = threadIdx.x;
    for (int i=t; i<2048; i+=512) sx[i>>6][i&63] = g_x[(size_t)xy*2048 + i]*(1.f/32768.f);
    __syncthreads();
    int c=t&63, kz=t>>6;
    float re=0.f, im=0.f;
    #pragma unroll
    for (int z=0; z<32; z++) {
        float v=sx[z][c]; float2 w=g_tw[(kz*z)&31];
        re += v*w.x; im += v*w.y;
    }
    g_A1[((size_t)xy*8+kz)*64+c] = make_float2(re,im);
}
__global__ void k_fft_y() {
    int X=blockIdx.x, kz=blockIdx.y;
    __shared__ float2 s[32][64];
    int t=threadIdx.x;
    for (int i=t; i<2048; i+=1024) s[i>>6][i&63] = g_A1[(((size_t)X*32+(i>>6))*8+kz)*64+(i&63)];
    __syncthreads();
    int c=t&63, kyi=t>>6;
    int ky = kyi<8 ? kyi : kyi+16;
    float re=0.f, im=0.f;
    #pragma unroll
    for (int y=0; y<32; y++) {
        float2 a=s[y][c]; float2 w=g_tw[(ky*y)&31];
        re += a.x*w.x - a.y*w.y;
        im += a.x*w.y + a.y*w.x;
    }
    g_A2[(((size_t)X*16+kyi)*8+kz)*64+c] = make_float2(re,im);
}
__global__ void k_fft_x() {
    int kyi=blockIdx.x, kz=blockIdx.y;
    __shared__ float2 s[32][64];
    int t=threadIdx.x;
    for (int i=t; i<2048; i+=1024) s[i>>6][i&63] = g_A2[(((size_t)(i>>6)*16+kyi)*8+kz)*64+(i&63)];
    __syncthreads();
    int c=t&63, kxi=t>>6;
    int kx = kxi<8 ? kxi : kxi+16;
    float re=0.f, im=0.f;
    #pragma unroll
    for (int X=0; X<32; X++) {
        float2 a=s[X][c]; float2 w=g_tw[(kx*X)&31];
        re += a.x*w.x - a.y*w.y;
        im += a.x*w.y + a.y*w.x;
    }
    g_XF[(((size_t)kxi*16+kyi)*8+kz)*64+c] = make_float2(re,im);
}
// spec weights: REAL float32 (L,4,H,H,M,M,M) — harness cast complex64->float32
// (imag dropped). wi = 0. Guarded by cap so a wrong interpretation can never IMA.
__global__ void k_spec(const float* __restrict__ W, int l, long long cap) {
    int bid=blockIdx.x;
    int ci=bid>>6, mx=(bid>>3)&7, my=bid&7;
    int kxi = mx + ((ci&2)?8:0);
    int kyi = my + ((ci&1)?8:0);
    __shared__ float2 sxf[8][64];
    int t=threadIdx.x;
    for (int i=t; i<512; i+=64) sxf[i>>6][i&63] = g_XF[(((size_t)kxi*16+kyi)*8+(i>>6))*64+(i&63)];
    __syncthreads();
    int o=t;
    float accr[8], acci[8];
    #pragma unroll
    for (int kz=0;kz<8;kz++){accr[kz]=0.f;acci[kz]=0.f;}
    size_t ebase = (size_t)(l*4+ci)*64*64*512 + (size_t)o*512 + (size_t)mx*64 + (size_t)my*8;
    for (int i=0;i<64;i++) {
        size_t e = ebase + (size_t)i*64*512;
        #pragma unroll
        for (int kz=0;kz<8;kz++) {
            long long idx = (long long)(e + kz);
            float wr = (idx < cap) ? W[idx] : 0.f;
            float2 a = sxf[kz][i];
            accr[kz] += a.x*wr;
            acci[kz] += a.y*wr;
        }
    }
    #pragma unroll
    for (int kz=0;kz<8;kz++)
        g_YF[(((size_t)kxi*16+kyi)*8+kz)*64+o] = make_float2(accr[kz],acci[kz]);
}
__global__ void k_ifft_x() {
    int kyi=blockIdx.x, kz=blockIdx.y;
    __shared__ float2 s[16][64];
    int t=threadIdx.x;
    if (t<1024) s[t>>6][t&63] = g_YF[(((size_t)(t>>6)*16+kyi)*8+kz)*64+(t&63)];
    __syncthreads();
    #pragma unroll
    for (int rep=0; rep<2; rep++) {
        int idx=t+rep*1024, X=idx>>6, c=idx&63;
        float re=0.f, im=0.f;
        #pragma unroll
        for (int kxi=0; kxi<16; kxi++) {
            int kx = kxi<8 ? kxi : kxi+16;
            float2 a=s[kxi][c]; float2 w=g_tw[(kx*X)&31];
            re += a.x*w.x + a.y*w.y;
            im += a.y*w.x - a.x*w.y;
        }
        g_B1[(((size_t)X*16+kyi)*8+kz)*64+c] = make_float2(re,im);
    }
}
__global__ void k_ifft_y() {
    int X=blockIdx.x, kz=blockIdx.y;
    __shared__ float2 s[16][64];
    int t=threadIdx.x;
    if (t<1024) s[t>>6][t&63] = g_B1[(((size_t)X*16+(t>>6))*8+kz)*64+(t&63)];
    __syncthreads();
    #pragma unroll
    for (int rep=0; rep<2; rep++) {
        int idx=t+rep*1024, y=idx>>6, c=idx&63;
        float re=0.f, im=0.f;
        #pragma unroll
        for (int kyi=0; kyi<16; kyi++) {
            int ky = kyi<8 ? kyi : kyi+16;
            float2 a=s[kyi][c]; float2 w=g_tw[(ky*y)&31];
            re += a.x*w.x + a.y*w.y;
            im += a.y*w.x - a.x*w.y;
        }
        g_B2[(((size_t)X*32+y)*8+kz)*64+c] = make_float2(re,im);
    }
}
__global__ void k_ifft_z(const float* __restrict__ specb, int dogelu) {
    int xy=blockIdx.x;
    __shared__ float2 s[8][64];
    int t=threadIdx.x;
    if (t<512) s[t>>6][t&63] = g_B2[((size_t)xy*8+(t>>6))*64+(t&63)];
    __syncthreads();
    #pragma unroll
    for (int rep=0; rep<4; rep++) {
        int idx=t+rep*512, z=idx>>6, c=idx&63;
        float val = s[0][c].x;
        #pragma unroll
        for (int kz=1; kz<8; kz++) {
            float2 a=s[kz][c]; float2 w=g_tw[(kz*z)&31];
            val += 2.f*(a.x*w.x + a.y*w.y);
        }
        size_t pt = (size_t)xy*32+z;
        float v = val + specb[c] + g_tmp[pt*64+c];
        if (dogelu) v = gelu_f(v);
        g_x[pt*64+c] = v;
    }
}

__global__ void k_gno1(const float* __restrict__ P, const float* __restrict__ Q,
                       const float* __restrict__ W, const float* __restrict__ b) {
    int p = blockIdx.x;
    if (p >= g_qoff[NQ]) return;
    int t = threadIdx.x;
    __shared__ float ft[6];
    if (t < 3) { int s=g_ps[p], q=g_pq[p]; ft[t]=P[s*3+t]; ft[3+t]=Q[q*3+t]; }
    __syncthreads();
    float v = b[t];
    #pragma unroll
    for (int d=0; d<6; d++) v += ft[d]*W[d*512+t];
    g_H1[(size_t)p*512+t] = gelu_f(v);
}
__global__ void k_reduce() {
    int q = blockIdx.x, c = threadIdx.x;
    int p0 = g_qoff[q], cnt = g_cnt[q];
    float acc = 0.f;
    for (int k=0; k<cnt; k++) {
        int p = p0+k, s = g_ps[p];
        acc += g_K3[(size_t)p*64+c] * g_x[(size_t)s*64+c];
    }
    float dn = cnt > 0 ? (float)cnt : 1.f;
    g_gno[q*64+c] = acc/dn;
}
__global__ void k_proj2(const float* __restrict__ W, const float* __restrict__ b,
                        float* __restrict__ out) {
    int q = blockIdx.x, t = threadIdx.x;
    __shared__ float sh[256];
    sh[t] = g_P1[q*256+t]*W[t];
    __syncthreads();
    for (int off=128; off>0; off>>=1) {
        if (t<off) sh[t]+=sh[t+off];
        __syncthreads();
    }
    if (t==0) out[q] = sh[0] + b[0];
}

static bool hx_capturing() {
    cudaStreamCaptureStatus st = cudaStreamCaptureStatusNone;
    cudaStreamIsCapturing((cudaStream_t)0, &st);
    return st != cudaStreamCaptureStatusNone;
}
#define CK(name) do { if (!cap_mode) { \
    cudaError_t e_ = cudaDeviceSynchronize(); \
    if (e_ != cudaSuccess) { \
        fprintf(stderr, "[fnogno] FAIL after %s: %s\n", name, cudaGetErrorString(e_)); \
        fflush(stderr); return; } } } while(0)

extern "C" void kernel_launch(void* const* d_in, const int* in_sizes, int n_in,
                              void* d_out, int out_size) {
    bool cap_mode = hx_capturing();

    // Confirmed layout (round-8 diagnostics): insertion order, 21 inputs,
    // spec_w at [7] as float32 x 33554432 (real part of complex64).
    const float* in_p  = (const float*)d_in[0];
    const float* out_p = (const float*)d_in[1];
    const float* f     = (const float*)d_in[2];
    const float* lw1   = (const float*)d_in[3];
    const float* lb1   = (const float*)d_in[4];
    const float* lw2   = (const float*)d_in[5];
    const float* lb2   = (const float*)d_in[6];
    const float* specw = (const float*)d_in[7];
    const float* specb = (const float*)d_in[8];
    const float* skw   = (const float*)d_in[9];
    const float* skb   = (const float*)d_in[10];
    const float* gw1   = (const float*)d_in[11];
    const float* gb1   = (const float*)d_in[12];
    const float* gw2   = (const float*)d_in[13];
    const float* gb2   = (const float*)d_in[14];
    const float* gw3   = (const float*)d_in[15];
    const float* gb3   = (const float*)d_in[16];
    const float* pw1   = (const float*)d_in[17];
    const float* pb1   = (const float*)d_in[18];
    const float* pw2   = (const float*)d_in[19];
    const float* pb2   = (const float*)d_in[20];
    long long spec_cap = (long long)in_sizes[7];   // 33554432 floats
    float* out = (float*)d_out;

    float *p_lift, *p_x, *p_tmp, *p_H1, *p_H2, *p_K3, *p_gno, *p_P1;
    cudaGetSymbolAddress((void**)&p_lift, g_lift);
    cudaGetSymbolAddress((void**)&p_x,    g_x);
    cudaGetSymbolAddress((void**)&p_tmp,  g_tmp);
    cudaGetSymbolAddress((void**)&p_H1,   g_H1);
    cudaGetSymbolAddress((void**)&p_H2,   g_H2);
    cudaGetSymbolAddress((void**)&p_K3,   g_K3);
    cudaGetSymbolAddress((void**)&p_gno,  g_gno);
    cudaGetSymbolAddress((void**)&p_P1,   g_P1);

    k_init_tw<<<1,32>>>();                      CK("init_tw");
    k_zero_cells<<<16,256>>>();                 CK("zero_cells");
    k_count<<<128,256>>>(in_p);                 CK("count");
    k_scan_cells<<<1,1024>>>();                 CK("scan_cells");
    k_scatter<<<128,256>>>(in_p);               CK("scatter");
    k_knn<<<32,128>>>(in_p, out_p);             CK("knn");
    k_scan_pairs<<<1,1024>>>();                 CK("scan_pairs");
    k_fill_pairs<<<32,128>>>(in_p, out_p);      CK("fill_pairs");

    k_lift1<<<N3,256>>>(f, in_p, lw1, lb1);     CK("lift1");
    k_gemm<64,64,16,4,4,false,false><<<dim3(1,512),256>>>(p_lift, lw2, lb2, p_x, N3, 64, 256);
    CK("lift2_gemm");

    for (int l=0; l<4; l++) {
        k_fft_z<<<1024,512>>>();                CK("fft_z");
        k_fft_y<<<dim3(32,8),1024>>>();         CK("fft_y");
        k_fft_x<<<dim3(16,8),1024>>>();         CK("fft_x");
        k_spec<<<256,64>>>(specw, l, spec_cap); CK("spec");
        k_gemm<64,64,16,4,4,false,false><<<dim3(1,512),256>>>(p_x, skw + l*64*64, skb + l*64, p_tmp, N3, 64, 64);
        CK("skip_gemm");
        k_ifft_x<<<dim3(16,8),1024>>>();        CK("ifft_x");
        k_ifft_y<<<dim3(32,8),1024>>>();        CK("ifft_y");
        k_ifft_z<<<1024,512>>>(specb + l*64, l<3 ? 1 : 0); CK("ifft_z");
    }

    k_gno1<<<NPAIR,512>>>(in_p, out_p, gw1, gb1); CK("gno1");
    k_gemm<64,64,16,4,4,true,true ><<<dim3(4,NPAIR/64),256>>>(p_H1, gw2, gb2, p_H2, NPAIR, 256, 512);
    CK("gno2_gemm");
    k_gemm<64,64,16,4,4,false,true><<<dim3(1,NPAIR/64),256>>>(p_H2, gw3, gb3, p_K3, NPAIR, 64, 256);
    CK("gno3_gemm");
    k_reduce<<<NQ,64>>>();                      CK("reduce");
    k_gemm<64,64,16,4,4,true,false><<<dim3(4,64),256>>>(p_gno, pw1, pb1, p_P1, NQ, 256, 64);
    CK("proj1_gemm");
    k_proj2<<<NQ,256>>>(pw2, pb2, out);         CK("proj2");
}

// round 10
// speedup vs baseline: 1.6897x; 1.6897x over previous
#include <cuda_runtime.h>
#include <math.h>
#include <stdio.h>

#define N3 32768
#define HH 64
#define NK 48
#define NQ 4096
#define NPAIR (NQ*NK)

__device__ float2 g_tw[32];
__device__ float  g_lift[N3*256];
__device__ float  g_x[N3*HH];
__device__ float  g_tmp[N3*HH];
__device__ float2 g_A1[1024*8*64];
__device__ float2 g_A2[32*16*8*64];
__device__ float2 g_XF[16*16*8*64];
__device__ float2 g_YF[16*16*8*64];
__device__ float2 g_B1[32*16*8*64];
__device__ float2 g_B2[1024*8*64];
__device__ int g_cellcnt[4096], g_celloff[4097], g_fill[4096], g_bin[N3];
__device__ int g_cnt[NQ], g_qoff[NQ+1], g_pq[NPAIR], g_ps[NPAIR];
__device__ int g_nbr[NQ*NK];
__device__ float g_H1[(size_t)NPAIR*512];
__device__ float g_H2[(size_t)NPAIR*256];
__device__ float g_K3[(size_t)NPAIR*64];
__device__ float g_gno[NQ*HH];
__device__ float g_P1[NQ*256];

__device__ __forceinline__ float gelu_f(float x) {
    float t = tanhf(0.7978845608028654f*(x + 0.044715f*x*x*x));
    return 0.5f*x*(1.0f + t);
}
__device__ __forceinline__ int cell_of(float x, float y, float z) {
    int ix = (int)(x*16.f); ix = ix<0?0:(ix>15?15:ix);
    int iy = (int)(y*16.f); iy = iy<0?0:(iy>15?15:iy);
    int iz = (int)(z*16.f); iz = iz<0?0:(iz>15?15:iz);
    return (ix*16+iy)*16+iz;
}

__global__ void k_init_tw() {
    int t = threadIdx.x;
    double a = -2.0*3.14159265358979323846*(double)t/32.0;
    g_tw[t] = make_float2((float)cos(a), (float)sin(a));
}
__global__ void k_zero_cells() {
    int i = blockIdx.x*blockDim.x + threadIdx.x;
    if (i < 4096) { g_cellcnt[i]=0; g_fill[i]=0; }
}
__global__ void k_count(const float* __restrict__ P) {
    int i = blockIdx.x*blockDim.x + threadIdx.x;
    if (i < N3) atomicAdd(&g_cellcnt[cell_of(P[i*3],P[i*3+1],P[i*3+2])], 1);
}
__device__ void scan4096(const int* __restrict__ in, int* __restrict__ out) {
    __shared__ int sh[1024];
    int t = threadIdx.x;
    int v0=in[t*4], v1=in[t*4+1], v2=in[t*4+2], v3=in[t*4+3];
    int p1=v0, p2=v0+v1, p3=p2+v2, s=p3+v3;
    sh[t]=s; __syncthreads();
    for (int off=1; off<1024; off<<=1) {
        int x = (t>=off) ? sh[t-off] : 0;
        __syncthreads(); sh[t]+=x; __syncthreads();
    }
    int base = sh[t]-s;
    out[t*4]=base; out[t*4+1]=base+p1; out[t*4+2]=base+p2; out[t*4+3]=base+p3;
    if (t==1023) out[4096]=sh[1023];
}
__global__ void k_scan_cells() { scan4096(g_cellcnt, g_celloff); }
__global__ void k_scan_pairs() { scan4096(g_cnt, g_qoff); }
__global__ void k_scatter(const float* __restrict__ P) {
    int i = blockIdx.x*blockDim.x + threadIdx.x;
    if (i >= N3) return;
    int c = cell_of(P[i*3],P[i*3+1],P[i*3+2]);
    g_bin[g_celloff[c] + atomicAdd(&g_fill[c],1)] = i;
}

__global__ void k_knn(const float* __restrict__ P, const float* __restrict__ Q) {
    int q = blockIdx.x*blockDim.x + threadIdx.x;
    if (q >= NQ) return;
    float qx=Q[q*3], qy=Q[q*3+1], qz=Q[q*3+2];
    int cx=(int)(qx*16.f); cx=cx<0?0:(cx>15?15:cx);
    int cy=(int)(qy*16.f); cy=cy<0?0:(cy>15?15:cy);
    int cz=(int)(qz*16.f); cz=cz<0?0:(cz>15?15:cz);
    const float R2 = 0.0036f;
    float dl[NK]; int il[NK]; int m=0;
    for (int ox=(cx>0?cx-1:0); ox<=(cx<15?cx+1:15); ox++)
    for (int oy=(cy>0?cy-1:0); oy<=(cy<15?cy+1:15); oy++)
    for (int oz=(cz>0?cz-1:0); oz<=(cz<15?cz+1:15); oz++) {
        int c=(ox*16+oy)*16+oz;
        int s1=g_celloff[c+1];
        for (int p=g_celloff[c]; p<s1; p++) {
            int s=g_bin[p];
            float dx=qx-P[s*3], dy=qy-P[s*3+1], dz=qz-P[s*3+2];
            float d2=dx*dx+dy*dy+dz*dz;
            if (d2 < R2) {
                if (m < NK) {
                    int pos=m++;
                    while (pos>0 && dl[pos-1]>d2) { dl[pos]=dl[pos-1]; il[pos]=il[pos-1]; pos--; }
                    dl[pos]=d2; il[pos]=s;
                } else if (d2 < dl[NK-1]) {
                    int pos=NK-1;
                    while (pos>0 && dl[pos-1]>d2) { dl[pos]=dl[pos-1]; il[pos]=il[pos-1]; pos--; }
                    dl[pos]=d2; il[pos]=s;
                }
            }
        }
    }
    g_cnt[q]=m;
    for (int k=0;k<m;k++) g_nbr[q*NK+k]=il[k];
}
__global__ void k_emit_pairs() {
    int q = blockIdx.x*blockDim.x + threadIdx.x;
    if (q >= NQ) return;
    int off=g_qoff[q], m=g_cnt[q];
    for (int k=0;k<m;k++) { g_pq[off+k]=q; g_ps[off+k]=g_nbr[q*NK+k]; }
}

__global__ void k_lift1(const float* __restrict__ F, const float* __restrict__ P,
                        const float* __restrict__ W, const float* __restrict__ b) {
    int p = blockIdx.x, t = threadIdx.x;
    __shared__ float ft[6];
    if (t < 3) { ft[t]=F[p*3+t]; ft[3+t]=P[p*3+t]; }
    __syncthreads();
    float v = b[t];
    #pragma unroll
    for (int d=0; d<6; d++) v += ft[d]*W[d*256+t];
    g_lift[(size_t)p*256+t] = gelu_f(v);
}

// ---- high-throughput SGEMM: C[M,N] = act(A[M,K] @ B[K,N] + b1) ----
// BM x BN tile, BK=8, TM x TN per thread, THREADS = (BM/TM)*(BN/TN) = 256.
template<int BM,int BN,int TM,int TN,bool DOGELU,bool PAIRLIM>
__global__ void k_gemm2(const float* __restrict__ A, const float* __restrict__ B,
                        const float* __restrict__ b1, float* __restrict__ C,
                        int M, int N, int K) {
    constexpr int BK = 8;
    constexpr int THREADS = (BM/TM)*(BN/TN);
    int Meff = PAIRLIM ? g_qoff[NQ] : M;
    int mBase = blockIdx.y*BM;
    if (mBase >= Meff) return;
    int nBase = blockIdx.x*BN;
    __shared__ __align__(16) float As[BK][BM];
    __shared__ __align__(16) float Bs[BK][BN];
    int tid = threadIdx.x;
    int tx = tid % (BN/TN);
    int ty = tid / (BN/TN);
    float acc[TM][TN];
    #pragma unroll
    for (int i=0;i<TM;i++) {
        #pragma unroll
        for (int j=0;j<TN;j++) acc[i][j]=0.f;
    }
    // A loader: BM*(BK/4) float4 slots; THREADS==BM*2 when BM=128
    int aRow = tid / (BK/4);
    int aKg  = (tid % (BK/4))*4;
    // B loader: BK*BN/4 float4 slots
    constexpr int BLD = BK*BN/4;
    int bRow = tid / (BN/4);
    int bCol = (tid % (BN/4))*4;
    for (int k0=0; k0<K; k0+=BK) {
        float4 av = make_float4(0.f,0.f,0.f,0.f);
        int m = mBase + aRow;
        if (m < Meff) av = *(const float4*)(A + (size_t)m*K + k0 + aKg);
        As[aKg+0][aRow]=av.x; As[aKg+1][aRow]=av.y;
        As[aKg+2][aRow]=av.z; As[aKg+3][aRow]=av.w;
        if (tid < BLD) {
            float4 bv = *(const float4*)(B + (size_t)(k0+bRow)*N + nBase + bCol);
            *(float4*)&Bs[bRow][bCol] = bv;
        }
        __syncthreads();
        #pragma unroll
        for (int kk=0; kk<BK; kk++) {
            float ra[TM], rb[TN];
            #pragma unroll
            for (int i=0;i<TM;i+=4) {
                float4 v = *(const float4*)&As[kk][ty*TM+i];
                ra[i]=v.x; ra[i+1]=v.y; ra[i+2]=v.z; ra[i+3]=v.w;
            }
            #pragma unroll
            for (int j=0;j<TN;j+=4) {
                float4 v = *(const float4*)&Bs[kk][tx*TN+j];
                rb[j]=v.x; rb[j+1]=v.y; rb[j+2]=v.z; rb[j+3]=v.w;
            }
            #pragma unroll
            for (int i=0;i<TM;i++) {
                #pragma unroll
                for (int j=0;j<TN;j++) acc[i][j] += ra[i]*rb[j];
            }
        }
        __syncthreads();
    }
    #pragma unroll
    for (int i=0;i<TM;i++) {
        int m = mBase + ty*TM + i;
        if (m >= Meff) continue;
        #pragma unroll
        for (int j=0;j<TN;j++) {
            int n = nBase + tx*TN + j;
            float v = acc[i][j] + b1[n];
            if (DOGELU) v = gelu_f(v);
            C[(size_t)m*N + n] = v;
        }
    }
}

__global__ void k_fft_z() {
    int xy = blockIdx.x;
    __shared__ float sx[32][64];
    int t = threadIdx.x;
    for (int i=t; i<2048; i+=512) sx[i>>6][i&63] = g_x[(size_t)xy*2048 + i]*(1.f/32768.f);
    __syncthreads();
    int c=t&63, kz=t>>6;
    float re=0.f, im=0.f;
    #pragma unroll
    for (int z=0; z<32; z++) {
        float v=sx[z][c]; float2 w=g_tw[(kz*z)&31];
        re += v*w.x; im += v*w.y;
    }
    g_A1[((size_t)xy*8+kz)*64+c] = make_float2(re,im);
}
__global__ void k_fft_y() {
    int X=blockIdx.x, kz=blockIdx.y;
    __shared__ float2 s[32][64];
    int t=threadIdx.x;
    for (int i=t; i<2048; i+=1024) s[i>>6][i&63] = g_A1[(((size_t)X*32+(i>>6))*8+kz)*64+(i&63)];
    __syncthreads();
    int c=t&63, kyi=t>>6;
    int ky = kyi<8 ? kyi : kyi+16;
    float re=0.f, im=0.f;
    #pragma unroll
    for (int y=0; y<32; y++) {
        float2 a=s[y][c]; float2 w=g_tw[(ky*y)&31];
        re += a.x*w.x - a.y*w.y;
        im += a.x*w.y + a.y*w.x;
    }
    g_A2[(((size_t)X*16+kyi)*8+kz)*64+c] = make_float2(re,im);
}
__global__ void k_fft_x() {
    int kyi=blockIdx.x, kz=blockIdx.y;
    __shared__ float2 s[32][64];
    int t=threadIdx.x;
    for (int i=t; i<2048; i+=1024) s[i>>6][i&63] = g_A2[(((size_t)(i>>6)*16+kyi)*8+kz)*64+(i&63)];
    __syncthreads();
    int c=t&63, kxi=t>>6;
    int kx = kxi<8 ? kxi : kxi+16;
    float re=0.f, im=0.f;
    #pragma unroll
    for (int X=0; X<32; X++) {
        float2 a=s[X][c]; float2 w=g_tw[(kx*X)&31];
        re += a.x*w.x - a.y*w.y;
        im += a.x*w.y + a.y*w.x;
    }
    g_XF[(((size_t)kxi*16+kyi)*8+kz)*64+c] = make_float2(re,im);
}
// REAL spec weights (harness cast complex64->float32, imag dropped).
// 256 threads: (o, quarter) split of the 64-term i-sum, smem reduction.
__global__ void k_spec(const float* __restrict__ W, int l) {
    int bid=blockIdx.x;
    int ci=bid>>6, mx=(bid>>3)&7, my=bid&7;
    int kxi = mx + ((ci&2)?8:0);
    int kyi = my + ((ci&1)?8:0);
    __shared__ float2 sxf[8][64];
    __shared__ float red[4][64][16];
    int t=threadIdx.x;
    int o = t & 63, qr = t >> 6;
    for (int i=t; i<512; i+=256) sxf[i>>6][i&63] = g_XF[(((size_t)kxi*16+kyi)*8+(i>>6))*64+(i&63)];
    __syncthreads();
    float accr[8], acci[8];
    #pragma unroll
    for (int kz=0;kz<8;kz++){accr[kz]=0.f;acci[kz]=0.f;}
    size_t ebase = (size_t)(l*4+ci)*64*64*512 + (size_t)o*512 + (size_t)mx*64 + (size_t)my*8;
    #pragma unroll 2
    for (int i = qr*16; i < qr*16+16; i++) {
        const float* wp = W + ebase + (size_t)i*64*512;
        float4 w0 = __ldg((const float4*)wp);
        float4 w1 = __ldg((const float4*)(wp+4));
        float wv[8] = {w0.x,w0.y,w0.z,w0.w,w1.x,w1.y,w1.z,w1.w};
        #pragma unroll
        for (int kz=0;kz<8;kz++) {
            float2 a = sxf[kz][i];
            accr[kz] += a.x*wv[kz];
            acci[kz] += a.y*wv[kz];
        }
    }
    #pragma unroll
    for (int kz=0;kz<8;kz++) {
        red[qr][o][kz*2]   = accr[kz];
        red[qr][o][kz*2+1] = acci[kz];
    }
    __syncthreads();
    if (qr == 0) {
        #pragma unroll
        for (int kz=0;kz<8;kz++) {
            float r = red[0][o][kz*2]   + red[1][o][kz*2]   + red[2][o][kz*2]   + red[3][o][kz*2];
            float m2= red[0][o][kz*2+1] + red[1][o][kz*2+1] + red[2][o][kz*2+1] + red[3][o][kz*2+1];
            g_YF[(((size_t)kxi*16+kyi)*8+kz)*64+o] = make_float2(r,m2);
        }
    }
}
__global__ void k_ifft_x() {
    int kyi=blockIdx.x, kz=blockIdx.y;
    __shared__ float2 s[16][64];
    int t=threadIdx.x;
    if (t<1024) s[t>>6][t&63] = g_YF[(((size_t)(t>>6)*16+kyi)*8+kz)*64+(t&63)];
    __syncthreads();
    #pragma unroll
    for (int rep=0; rep<2; rep++) {
        int idx=t+rep*1024, X=idx>>6, c=idx&63;
        float re=0.f, im=0.f;
        #pragma unroll
        for (int kxi=0; kxi<16; kxi++) {
            int kx = kxi<8 ? kxi : kxi+16;
            float2 a=s[kxi][c]; float2 w=g_tw[(kx*X)&31];
            re += a.x*w.x + a.y*w.y;
            im += a.y*w.x - a.x*w.y;
        }
        g_B1[(((size_t)X*16+kyi)*8+kz)*64+c] = make_float2(re,im);
    }
}
__global__ void k_ifft_y() {
    int X=blockIdx.x, kz=blockIdx.y;
    __shared__ float2 s[16][64];
    int t=threadIdx.x;
    if (t<1024) s[t>>6][t&63] = g_B1[(((size_t)X*16+(t>>6))*8+kz)*64+(t&63)];
    __syncthreads();
    #pragma unroll
    for (int rep=0; rep<2; rep++) {
        int idx=t+rep*1024, y=idx>>6, c=idx&63;
        float re=0.f, im=0.f;
        #pragma unroll
        for (int kyi=0; kyi<16; kyi++) {
            int ky = kyi<8 ? kyi : kyi+16;
            float2 a=s[kyi][c]; float2 w=g_tw[(ky*y)&31];
            re += a.x*w.x + a.y*w.y;
            im += a.y*w.x - a.x*w.y;
        }
        g_B2[(((size_t)X*32+y)*8+kz)*64+c] = make_float2(re,im);
    }
}
__global__ void k_ifft_z(const float* __restrict__ specb, int dogelu) {
    int xy=blockIdx.x;
    __shared__ float2 s[8][64];
    int t=threadIdx.x;
    if (t<512) s[t>>6][t&63] = g_B2[((size_t)xy*8+(t>>6))*64+(t&63)];
    __syncthreads();
    #pragma unroll
    for (int rep=0; rep<4; rep++) {
        int idx=t+rep*512, z=idx>>6, c=idx&63;
        float val = s[0][c].x;
        #pragma unroll
        for (int kz=1; kz<8; kz++) {
            float2 a=s[kz][c]; float2 w=g_tw[(kz*z)&31];
            val += 2.f*(a.x*w.x + a.y*w.y);
        }
        size_t pt = (size_t)xy*32+z;
        float v = val + specb[c] + g_tmp[pt*64+c];
        if (dogelu) v = gelu_f(v);
        g_x[pt*64+c] = v;
    }
}

__global__ void k_gno1(const float* __restrict__ P, const float* __restrict__ Q,
                       const float* __restrict__ W, const float* __restrict__ b) {
    int p = blockIdx.x;
    if (p >= g_qoff[NQ]) return;
    int t = threadIdx.x;
    __shared__ float ft[6];
    if (t < 3) { int s=g_ps[p], q=g_pq[p]; ft[t]=P[s*3+t]; ft[3+t]=Q[q*3+t]; }
    __syncthreads();
    float v = b[t];
    #pragma unroll
    for (int d=0; d<6; d++) v += ft[d]*W[d*512+t];
    g_H1[(size_t)p*512+t] = gelu_f(v);
}
__global__ void k_reduce() {
    int q = blockIdx.x, c = threadIdx.x;
    int p0 = g_qoff[q], cnt = g_cnt[q];
    float acc = 0.f;
    for (int k=0; k<cnt; k++) {
        int p = p0+k, s = g_ps[p];
        acc += g_K3[(size_t)p*64+c] * g_x[(size_t)s*64+c];
    }
    float dn = cnt > 0 ? (float)cnt : 1.f;
    g_gno[q*64+c] = acc/dn;
}
__global__ void k_proj2(const float* __restrict__ W, const float* __restrict__ b,
                        float* __restrict__ out) {
    int q = blockIdx.x, t = threadIdx.x;
    __shared__ float sh[256];
    sh[t] = g_P1[q*256+t]*W[t];
    __syncthreads();
    for (int off=128; off>0; off>>=1) {
        if (t<off) sh[t]+=sh[t+off];
        __syncthreads();
    }
    if (t==0) out[q] = sh[0] + b[0];
}

static bool hx_capturing() {
    cudaStreamCaptureStatus st = cudaStreamCaptureStatusNone;
    cudaStreamIsCapturing((cudaStream_t)0, &st);
    return st != cudaStreamCaptureStatusNone;
}
#define CK(name) do { if (!cap_mode) { \
    cudaError_t e_ = cudaDeviceSynchronize(); \
    if (e_ != cudaSuccess) { \
        fprintf(stderr, "[fnogno] FAIL after %s: %s\n", name, cudaGetErrorString(e_)); \
        fflush(stderr); return; } } } while(0)

extern "C" void kernel_launch(void* const* d_in, const int* in_sizes, int n_in,
                              void* d_out, int out_size) {
    bool cap_mode = hx_capturing();

    const float* in_p  = (const float*)d_in[0];
    const float* out_p = (const float*)d_in[1];
    const float* f     = (const float*)d_in[2];
    const float* lw1   = (const float*)d_in[3];
    const float* lb1   = (const float*)d_in[4];
    const float* lw2   = (const float*)d_in[5];
    const float* lb2   = (const float*)d_in[6];
    const float* specw = (const float*)d_in[7];
    const float* specb = (const float*)d_in[8];
    const float* skw   = (const float*)d_in[9];
    const float* skb   = (const float*)d_in[10];
    const float* gw1   = (const float*)d_in[11];
    const float* gb1   = (const float*)d_in[12];
    const float* gw2   = (const float*)d_in[13];
    const float* gb2   = (const float*)d_in[14];
    const float* gw3   = (const float*)d_in[15];
    const float* gb3   = (const float*)d_in[16];
    const float* pw1   = (const float*)d_in[17];
    const float* pb1   = (const float*)d_in[18];
    const float* pw2   = (const float*)d_in[19];
    const float* pb2   = (const float*)d_in[20];
    float* out = (float*)d_out;

    float *p_lift, *p_x, *p_tmp, *p_H1, *p_H2, *p_K3, *p_gno, *p_P1;
    cudaGetSymbolAddress((void**)&p_lift, g_lift);
    cudaGetSymbolAddress((void**)&p_x,    g_x);
    cudaGetSymbolAddress((void**)&p_tmp,  g_tmp);
    cudaGetSymbolAddress((void**)&p_H1,   g_H1);
    cudaGetSymbolAddress((void**)&p_H2,   g_H2);
    cudaGetSymbolAddress((void**)&p_K3,   g_K3);
    cudaGetSymbolAddress((void**)&p_gno,  g_gno);
    cudaGetSymbolAddress((void**)&p_P1,   g_P1);

    k_init_tw<<<1,32>>>();                      CK("init_tw");
    k_zero_cells<<<16,256>>>();                 CK("zero_cells");
    k_count<<<128,256>>>(in_p);                 CK("count");
    k_scan_cells<<<1,1024>>>();                 CK("scan_cells");
    k_scatter<<<128,256>>>(in_p);               CK("scatter");
    k_knn<<<32,128>>>(in_p, out_p);             CK("knn");
    k_scan_pairs<<<1,1024>>>();                 CK("scan_pairs");
    k_emit_pairs<<<32,128>>>();                 CK("emit_pairs");

    k_lift1<<<N3,256>>>(f, in_p, lw1, lb1);     CK("lift1");
    k_gemm2<128,64,8,4,false,false><<<dim3(1,N3/128),256>>>(p_lift, lw2, lb2, p_x, N3, 64, 256);
    CK("lift2_gemm");

    for (int l=0; l<4; l++) {
        k_fft_z<<<1024,512>>>();                CK("fft_z");
        k_fft_y<<<dim3(32,8),1024>>>();         CK("fft_y");
        k_fft_x<<<dim3(16,8),1024>>>();         CK("fft_x");
        k_spec<<<256,256>>>(specw, l);          CK("spec");
        k_gemm2<128,64,8,4,false,false><<<dim3(1,N3/128),256>>>(p_x, skw + l*64*64, skb + l*64, p_tmp, N3, 64, 64);
        CK("skip_gemm");
        k_ifft_x<<<dim3(16,8),1024>>>();        CK("ifft_x");
        k_ifft_y<<<dim3(32,8),1024>>>();        CK("ifft_y");
        k_ifft_z<<<1024,512>>>(specb + l*64, l<3 ? 1 : 0); CK("ifft_z");
    }

    k_gno1<<<NPAIR,512>>>(in_p, out_p, gw1, gb1); CK("gno1");
    k_gemm2<128,128,8,8,true,true ><<<dim3(2,NPAIR/128),256>>>(p_H1, gw2, gb2, p_H2, NPAIR, 256, 512);
    CK("gno2_gemm");
    k_gemm2<128,64,8,4,false,true><<<dim3(1,NPAIR/128),256>>>(p_H2, gw3, gb3, p_K3, NPAIR, 64, 256);
    CK("gno3_gemm");
    k_reduce<<<NQ,64>>>();                      CK("reduce");
    k_gemm2<128,128,8,8,true,false><<<dim3(2,NQ/128),256>>>(p_gno, pw1, pb1, p_P1, NQ, 256, 64);
    CK("proj1_gemm");
    k_proj2<<<NQ,256>>>(pw2, pb2, out);         CK("proj2");
}